// round 4
// baseline (speedup 1.0000x reference)
#include <cuda_runtime.h>

// B=8, MSP=2048, D=512, A=64, NB=5
// Inputs: e_output [8*2048*512] f32, W_ll [64*2048] f32, b_ll [64] f32,
//         W_fl [5*1024] f32, b_fl [5] f32, (max_atoms scalar unused)
// Output: [8,64,64,5] f32.
//
// Exact contraction reordering:
//   Wc[n,d]   = W_fl[n,d] + W_fl[n,512+d]
//   S[n]      = sum_d Wc[n,d]
//   t[b,s,n]  = sum_d e[b,s,d] * Wc[n,d]
//   out[b,a,n]= sum_s W_ll[a,s] * t[b,s,n] + b_ll[a]*S[n] + b_fl[n]
//   final[b,i,j,n] = out[b,i,n]
//
// Fused: kernel 1 computes t per row AND accumulates W_ll[a,s]*t into
// warp-private smem acc, then REDGs block partials into g_out[2560].
// Kernel 2 adds biases, broadcast-writes, and re-zeros g_out for the
// next graph replay (deterministic init: __device__ globals start zeroed,
// and the only reader of each g_out element re-zeros it after reading).

#define DVAL   512
#define NB     5
#define AVAL   64
#define BVAL   8
#define MSP    2048
#define SCHUNK 64            // s per block in kernel 1

__device__ float g_S[NB];
__device__ float g_out[BVAL * AVAL * NB];   // 2560 floats, zero at start of every launch

// ---------------------------------------------------------------------------
// Kernel 1: fused t + partial-out accumulation.
// grid = (MSP/SCHUNK=32, 8 b), block = 256 (8 warps, 8 s-rows per warp).
// smem: Wc stage (10 KB) + 8 warp-private acc[64][5] (10.2 KB) -> 2 blocks/SM.
// ---------------------------------------------------------------------------
__global__ __launch_bounds__(256, 2) void fused_kernel(const float* __restrict__ e,
                                                       const float* __restrict__ W_fl,
                                                       const float* __restrict__ W_ll) {
    __shared__ float wcs[NB * DVAL];          // 10 KB
    __shared__ float acc[8][AVAL * NB];       // 8 x 320 floats

    const int tid  = threadIdx.x;
    const int lane = tid & 31;
    const int warp = tid >> 5;
    const int b    = blockIdx.y;

    // Build Wc in smem
    for (int i = tid; i < NB * DVAL; i += 256) {
        int n = i / DVAL, d = i - n * DVAL;
        wcs[i] = W_fl[n * 1024 + d] + W_fl[n * 1024 + 512 + d];
    }
    __syncthreads();

    // One warp on the chip computes S[n]
    if (blockIdx.x == 0 && b == 0 && warp == 0) {
        #pragma unroll
        for (int n = 0; n < NB; n++) {
            float s = 0.f;
            for (int d = lane; d < DVAL; d += 32) s += wcs[n * DVAL + d];
            #pragma unroll
            for (int off = 16; off > 0; off >>= 1)
                s += __shfl_xor_sync(0xFFFFFFFFu, s, off);
            if (lane == 0) g_S[n] = s;
        }
    }

    // Per-lane register copy of Wc: lane handles d = r*128 + lane*4 .. +3
    float4 wc[4][NB];
    #pragma unroll
    for (int r = 0; r < 4; r++)
        #pragma unroll
        for (int n = 0; n < NB; n++)
            wc[r][n] = *(const float4*)&wcs[n * DVAL + r * 128 + lane * 4];

    // Zero this warp's accumulator (warp-private: no sync needed)
    float* accp = acc[warp];
    for (int i = lane; i < AVAL * NB; i += 32) accp[i] = 0.f;

    const int s_base = blockIdx.x * SCHUNK + warp * 8;
    const float* wl0p = W_ll + (size_t)lane * MSP;
    const float* wl1p = W_ll + (size_t)(lane + 32) * MSP;

    #pragma unroll 2
    for (int i = 0; i < 8; i++) {
        const int s   = s_base + i;
        const float4* er = (const float4*)(e + ((size_t)b * MSP + s) * DVAL);

        // Front-batched loads: 4 LDG.128 per lane + 2 W_ll (L1-resident)
        float4 ev[4];
        #pragma unroll
        for (int r = 0; r < 4; r++) ev[r] = er[r * 32 + lane];
        const float wl0 = __ldg(&wl0p[s]);
        const float wl1 = __ldg(&wl1p[s]);

        float t[NB];
        #pragma unroll
        for (int n = 0; n < NB; n++) t[n] = 0.f;

        #pragma unroll
        for (int r = 0; r < 4; r++) {
            #pragma unroll
            for (int n = 0; n < NB; n++) {
                t[n] += ev[r].x * wc[r][n].x;
                t[n] += ev[r].y * wc[r][n].y;
                t[n] += ev[r].z * wc[r][n].z;
                t[n] += ev[r].w * wc[r][n].w;
            }
        }

        // Butterfly: every lane ends with the full t[s,n]
        #pragma unroll
        for (int n = 0; n < NB; n++) {
            #pragma unroll
            for (int off = 16; off > 0; off >>= 1)
                t[n] += __shfl_xor_sync(0xFFFFFFFFu, t[n], off);
        }

        // Scatter: lane owns a = lane and a = lane+32 (stride-5 -> conflict-free)
        float* p0 = &accp[lane * NB];
        float* p1 = &accp[(lane + 32) * NB];
        #pragma unroll
        for (int n = 0; n < NB; n++) {
            p0[n] += wl0 * t[n];
            p1[n] += wl1 * t[n];
        }
    }
    __syncthreads();

    // Combine 8 warp partials, REDG into g_out[b]
    for (int idx = tid; idx < AVAL * NB; idx += 256) {
        float s = 0.f;
        #pragma unroll
        for (int w = 0; w < 8; w++) s += acc[w][idx];
        atomicAdd(&g_out[b * (AVAL * NB) + idx], s);
    }
}

// ---------------------------------------------------------------------------
// Kernel 2: biases + broadcast over j + re-zero g_out.
// grid = (16 a-quads, 8 b), block = 256. Each block: 20 g_out reads,
// 1280 contiguous output floats.
// ---------------------------------------------------------------------------
__global__ __launch_bounds__(256) void bcast_kernel(const float* __restrict__ b_ll,
                                                    const float* __restrict__ b_fl,
                                                    float* __restrict__ out) {
    __shared__ float v[4 * NB];
    const int b   = blockIdx.y;
    const int a0  = blockIdx.x * 4;
    const int tid = threadIdx.x;

    if (tid < 4 * NB) {
        const int al = tid / NB, n = tid - al * NB;
        const int a  = a0 + al;
        float* gp = &g_out[b * (AVAL * NB) + a * NB + n];
        float x = *gp;
        *gp = 0.f;                                   // reset for next replay
        v[tid] = x + b_ll[a] * g_S[n] + b_fl[n];
    }
    __syncthreads();

    float* base = out + ((size_t)(b * AVAL + a0)) * (AVAL * NB);
    #pragma unroll
    for (int k = 0; k < 5; k++) {
        const int idx = tid + k * 256;               // 0..1279
        const int al  = idx / (AVAL * NB);
        const int n   = idx % NB;
        base[idx] = v[al * NB + n];
    }
}

// ---------------------------------------------------------------------------
extern "C" void kernel_launch(void* const* d_in, const int* in_sizes, int n_in,
                              void* d_out, int out_size) {
    const float* e    = (const float*)d_in[0];
    const float* W_ll = (const float*)d_in[1];
    const float* b_ll = (const float*)d_in[2];
    const float* W_fl = (const float*)d_in[3];
    const float* b_fl = (const float*)d_in[4];
    float* out = (float*)d_out;

    fused_kernel<<<dim3(MSP / SCHUNK, BVAL), 256>>>(e, W_fl, W_ll);
    bcast_kernel<<<dim3(16, BVAL), 256>>>(b_ll, b_fl, out);
}

// round 5
// speedup vs baseline: 1.2480x; 1.2480x over previous
#include <cuda_runtime.h>

// B=8, MSP=2048, D=512, A=64, NB=5
// Exact contraction reordering:
//   Wc[n,d]   = W_fl[n,d] + W_fl[n,512+d]
//   S[n]      = sum_d Wc[n,d]
//   t[b,s,n]  = sum_d e[b,s,d] * Wc[n,d]
//   out[b,a,n]= sum_s W_ll[a,s] * t[b,s,n] + b_ll[a]*S[n] + b_fl[n]
//   final[b,i,j,n] = out[b,i,n]

#define NROWS  16384      // B * MSP
#define DVAL   512
#define NB     5
#define AVAL   64
#define BVAL   8
#define MSP    2048

__device__ float g_S[NB];
__device__ float g_t[NROWS * NB];          // 320 KB scratch (L2-resident)

// ---------------------------------------------------------------------------
// Kernel 1: t[b,s,n] = <e_row, Wc[n]>.  One warp per row, software-pipelined:
// next row's 4 LDG.128 are issued before the current row's FFMA/SHFL tail.
// Wc held in 80 regs/thread. Block 0 warp 0 computes S.
// ---------------------------------------------------------------------------
__global__ __launch_bounds__(256, 2) void t_kernel(const float* __restrict__ e,
                                                   const float* __restrict__ W_fl) {
    __shared__ float wcs[NB * DVAL];   // 10 KB
    const int tid  = threadIdx.x;
    const int lane = tid & 31;
    const int warp = tid >> 5;

    for (int i = tid; i < NB * DVAL; i += 256) {
        int n = i / DVAL, d = i - n * DVAL;
        wcs[i] = W_fl[n * 1024 + d] + W_fl[n * 1024 + 512 + d];
    }
    __syncthreads();

    if (blockIdx.x == 0 && warp == 0) {
        #pragma unroll
        for (int n = 0; n < NB; n++) {
            float s = 0.f;
            for (int d = lane; d < DVAL; d += 32) s += wcs[n * DVAL + d];
            #pragma unroll
            for (int off = 16; off > 0; off >>= 1)
                s += __shfl_xor_sync(0xFFFFFFFFu, s, off);
            if (lane == 0) g_S[n] = s;
        }
    }

    // Per-lane register copy of Wc: lane handles d = r*128 + lane*4 .. +3
    float4 wc[4][NB];
    #pragma unroll
    for (int r = 0; r < 4; r++)
        #pragma unroll
        for (int n = 0; n < NB; n++)
            wc[r][n] = *(const float4*)&wcs[n * DVAL + r * 128 + lane * 4];

    const int gw = blockIdx.x * 8 + warp;
    const int nw = gridDim.x * 8;

    // ---- software-pipelined row loop ----
    int row = gw;
    float4 ev[4];
    if (row < NROWS) {
        const float4* er = (const float4*)(e + (size_t)row * DVAL);
        #pragma unroll
        for (int r = 0; r < 4; r++) ev[r] = er[r * 32 + lane];
    }

    while (row < NROWS) {
        const int nxt = row + nw;

        // Prefetch next row while current row computes
        float4 ev2[4];
        if (nxt < NROWS) {
            const float4* er2 = (const float4*)(e + (size_t)nxt * DVAL);
            #pragma unroll
            for (int r = 0; r < 4; r++) ev2[r] = er2[r * 32 + lane];
        }

        float acc[NB];
        #pragma unroll
        for (int n = 0; n < NB; n++) acc[n] = 0.f;

        #pragma unroll
        for (int r = 0; r < 4; r++) {
            #pragma unroll
            for (int n = 0; n < NB; n++) {
                acc[n] += ev[r].x * wc[r][n].x;
                acc[n] += ev[r].y * wc[r][n].y;
                acc[n] += ev[r].z * wc[r][n].z;
                acc[n] += ev[r].w * wc[r][n].w;
            }
        }

        #pragma unroll
        for (int n = 0; n < NB; n++) {
            #pragma unroll
            for (int off = 16; off > 0; off >>= 1)
                acc[n] += __shfl_xor_sync(0xFFFFFFFFu, acc[n], off);
        }

        if (lane == 0) {
            float* tp = &g_t[row * NB];
            #pragma unroll
            for (int n = 0; n < NB; n++) tp[n] = acc[n];
        }

        #pragma unroll
        for (int r = 0; r < 4; r++) ev[r] = ev2[r];
        row = nxt;
    }
}

// ---------------------------------------------------------------------------
// Kernel 2: out[b,a,n] + broadcast over j.  No smem staging — t read
// straight from L2.  grid = (64 a, 8 b) = 512 blocks, 256 threads
// (8 warps, each warp reduces a 256-wide s-chunk for the block's single a).
// ---------------------------------------------------------------------------
__global__ __launch_bounds__(256) void out_kernel(const float* __restrict__ W_ll,
                                                  const float* __restrict__ b_ll,
                                                  const float* __restrict__ b_fl,
                                                  float* __restrict__ out) {
    __shared__ float partial[8 * NB];
    __shared__ float v[NB];
    const int a    = blockIdx.x;
    const int b    = blockIdx.y;
    const int tid  = threadIdx.x;
    const int lane = tid & 31;
    const int w    = tid >> 5;

    const float* wrow  = W_ll + (size_t)a * MSP + w * 256;
    const float* tbase = g_t + ((size_t)b * MSP + w * 256) * NB;

    // Front-batch the 8 W_ll loads (coalesced, L2-resident)
    float wv[8];
    #pragma unroll
    for (int k = 0; k < 8; k++) wv[k] = wrow[lane + 32 * k];

    float a0 = 0.f, a1 = 0.f, a2 = 0.f, a3 = 0.f, a4 = 0.f;
    #pragma unroll
    for (int k = 0; k < 8; k++) {
        const float* tp = &tbase[(lane + 32 * k) * NB];
        a0 += wv[k] * tp[0];
        a1 += wv[k] * tp[1];
        a2 += wv[k] * tp[2];
        a3 += wv[k] * tp[3];
        a4 += wv[k] * tp[4];
    }
    #pragma unroll
    for (int off = 16; off > 0; off >>= 1) {
        a0 += __shfl_xor_sync(0xFFFFFFFFu, a0, off);
        a1 += __shfl_xor_sync(0xFFFFFFFFu, a1, off);
        a2 += __shfl_xor_sync(0xFFFFFFFFu, a2, off);
        a3 += __shfl_xor_sync(0xFFFFFFFFu, a3, off);
        a4 += __shfl_xor_sync(0xFFFFFFFFu, a4, off);
    }
    if (lane == 0) {
        float* pp = &partial[w * NB];
        pp[0] = a0; pp[1] = a1; pp[2] = a2; pp[3] = a3; pp[4] = a4;
    }
    __syncthreads();

    if (tid < NB) {
        float s = 0.f;
        #pragma unroll
        for (int q = 0; q < 8; q++) s += partial[q * NB + tid];
        v[tid] = s + b_ll[a] * g_S[tid] + b_fl[tid];
    }
    __syncthreads();

    // Broadcast over j: 64 * 5 = 320 contiguous floats for this (b,a)
    float* base = out + ((size_t)(b * AVAL + a)) * (AVAL * NB);
    #pragma unroll
    for (int k = 0; k < 2; k++) {
        int idx = tid + k * 256;
        if (idx < AVAL * NB) base[idx] = v[idx % NB];
    }
}

// ---------------------------------------------------------------------------
extern "C" void kernel_launch(void* const* d_in, const int* in_sizes, int n_in,
                              void* d_out, int out_size) {
    const float* e    = (const float*)d_in[0];
    const float* W_ll = (const float*)d_in[1];
    const float* b_ll = (const float*)d_in[2];
    const float* W_fl = (const float*)d_in[3];
    const float* b_fl = (const float*)d_in[4];
    float* out = (float*)d_out;

    t_kernel<<<296, 256>>>(e, W_fl);
    out_kernel<<<dim3(AVAL, BVAL), 256>>>(W_ll, b_ll, b_fl, out);
}